// round 8
// baseline (speedup 1.0000x reference)
#include <cuda_runtime.h>
#include <cstdint>

#define B 128
#define L 200
#define D 256
#define V_SIZE 50000
#define THREADS 256

#define NSCORE 4                      // score blocks per batch
#define NZERO  8                      // zero blocks per batch
#define BPB    (NSCORE + NZERO)       // 12 blocks per batch
#define ROWS_PER_BLK (L / NSCORE)     // 50
#define V4     (V_SIZE / 4)           // 12500 float4 per batch row

__device__ float g_scores[B * L];
__device__ int   g_cnt[B];            // zero at load; each launch: ->12 then reset to 0

__global__ void __launch_bounds__(THREADS)
fused_overlap_kernel(const float* __restrict__ w_es,
                     const float* __restrict__ score_v,
                     const int* __restrict__ x,
                     float* __restrict__ out,
                     int write_tail)
{
    // All shared vars at function scope, 16B-aligned where vector-accessed.
    __shared__ __align__(16) float sv[D];
    __shared__ __align__(16) int   xsh[THREADS];
    __shared__ float redm[8];
    __shared__ float reds[8];
    __shared__ int   s_islast;

    int blk = blockIdx.x;
    int tid = threadIdx.x;
    int b = blk / BPB;
    int r = blk % BPB;

    if (r < NSCORE) {
        // ---- score block: 50 dot products (proven K1 pattern) ----
        sv[tid] = score_v[tid];       // D == THREADS
        __syncthreads();

        int wid = tid >> 5;
        int lane = tid & 31;
        int l0 = r * ROWS_PER_BLK;
        const float* base = w_es + ((size_t)b * L + l0) * D;
        const float4* sv4 = reinterpret_cast<const float4*>(sv);

        for (int l = wid; l < ROWS_PER_BLK; l += 8) {
            const float4* row4 = reinterpret_cast<const float4*>(base + (size_t)l * D);
            float acc = 0.f;
            #pragma unroll
            for (int k = 0; k < 2; k++) {
                int d = lane + 32 * k;
                float4 a = row4[d];
                float4 s = sv4[d];
                acc = fmaf(a.x, s.x, acc);
                acc = fmaf(a.y, s.y, acc);
                acc = fmaf(a.z, s.z, acc);
                acc = fmaf(a.w, s.w, acc);
            }
            #pragma unroll
            for (int off = 16; off > 0; off >>= 1)
                acc += __shfl_xor_sync(0xFFFFFFFF, acc, off);
            if (lane == 0) g_scores[(size_t)b * L + l0 + l] = acc;
        }
    } else {
        // ---- zero block: 1/8 of batch row b, float4 strided ----
        // out + b*V_SIZE is 16B-aligned: b*50000*4 = b*200000 bytes, 200000%16==0
        int z = r - NSCORE;           // 0..7
        float4* p = reinterpret_cast<float4*>(out + (size_t)b * V_SIZE);
        float4 zero = make_float4(0.f, 0.f, 0.f, 0.f);
        for (int i = z * THREADS + tid; i < V4; i += NZERO * THREADS)
            p[i] = zero;
    }

    // ---- completion counter: 12th arriver for batch b runs the epilogue ----
    __threadfence();                  // release: zeroes/scores visible before count
    __syncthreads();
    if (tid == 0) {
        int old = atomicAdd(&g_cnt[b], 1);
        s_islast = (old == BPB - 1);
    }
    __syncthreads();
    if (!s_islast) return;
    __threadfence();                  // acquire: see all 12 blocks' writes

    // ---- epilogue: softmax + branchless dedup + conflict-free scatter ----
    {
        int wid = tid >> 5;
        int lane = tid & 31;

        int   xv = (tid < L) ? x[(size_t)b * L + tid] : -1;
        float v  = (tid < L) ? g_scores[(size_t)b * L + tid] : -3.402823466e38f;
        xsh[tid] = xv;
        __syncthreads();

        int last = 1;
        #pragma unroll 8
        for (int l = tid + 1; l < L; l++)
            last &= (xsh[l] != xv);

        float m = v;
        #pragma unroll
        for (int off = 16; off > 0; off >>= 1)
            m = fmaxf(m, __shfl_xor_sync(0xFFFFFFFF, m, off));
        if (lane == 0) redm[wid] = m;
        __syncthreads();
        float mx = redm[0];
        #pragma unroll
        for (int i = 1; i < 8; i++) mx = fmaxf(mx, redm[i]);

        float e = (tid < L) ? __expf(v - mx) : 0.f;
        float s = e;
        #pragma unroll
        for (int off = 16; off > 0; off >>= 1)
            s += __shfl_xor_sync(0xFFFFFFFF, s, off);
        if (lane == 0) reds[wid] = s;
        __syncthreads();
        float tot = reds[0];
        #pragma unroll
        for (int i = 1; i < 8; i++) tot += reds[i];

        float w = e * (1.0f / tot);

        if (tid < L) {
            if (write_tail)
                out[(size_t)B * V_SIZE + (size_t)b * L + tid] = w;
            if (last && (unsigned)xv < V_SIZE)
                out[(size_t)b * V_SIZE + xv] = w;
        }

        if (tid == 0) g_cnt[b] = 0;   // reset for next graph replay
    }
}

extern "C" void kernel_launch(void* const* d_in, const int* in_sizes, int n_in,
                              void* d_out, int out_size)
{
    const float* w_es = (const float*)d_in[0];
    const float* score_v = (const float*)d_in[1];
    const int* x = (const int*)d_in[2];
    float* out = (float*)d_out;

    int write_tail = (out_size >= B * V_SIZE + B * L) ? 1 : 0;

    fused_overlap_kernel<<<B * BPB, THREADS>>>(w_es, score_v, x, out, write_tail);
}

// round 9
// speedup vs baseline: 1.1659x; 1.1659x over previous
#include <cuda_runtime.h>
#include <cstdint>

#define B 128
#define L 200
#define D 256
#define V_SIZE 50000
#define THREADS 256

#define SPLIT 8                       // score blocks per batch
#define ROWS_PER_BLK (L / SPLIT)      // 25
#define SCORE_BLOCKS (B * SPLIT)      // 1024
#define ZERO_BLOCKS 1024
#define DEDUP_BLOCKS B                // 128
#define K1_GRID (SCORE_BLOCKS + ZERO_BLOCKS + DEDUP_BLOCKS)

__device__ float g_scores[B * L];
__device__ int   g_sidx[B * L];       // last-occurrence ? idx : -1

// K1: [0,1024) score blocks; [1024,2048) zero blocks; [2048,2176) dedup blocks.
__global__ void __launch_bounds__(THREADS)
stream_kernel(const float* __restrict__ w_es,
              const float* __restrict__ score_v,
              const int* __restrict__ x,
              float* __restrict__ out)
{
    __shared__ __align__(16) float sv[D];      // score path
    __shared__ __align__(16) int   xsh[THREADS]; // dedup path

    int blk = blockIdx.x;
    int tid = threadIdx.x;

    if (blk < SCORE_BLOCKS) {
        // ---- score block: 25 dot products (warp per row, float4) ----
        int b = blk / SPLIT;
        int l0 = (blk % SPLIT) * ROWS_PER_BLK;

        sv[tid] = score_v[tid];       // D == THREADS
        __syncthreads();

        int wid = tid >> 5;
        int lane = tid & 31;
        const float* base = w_es + ((size_t)b * L + l0) * D;
        const float4* sv4 = reinterpret_cast<const float4*>(sv);

        for (int l = wid; l < ROWS_PER_BLK; l += 8) {
            const float4* row4 = reinterpret_cast<const float4*>(base + (size_t)l * D);
            float acc = 0.f;
            #pragma unroll
            for (int k = 0; k < 2; k++) {
                int d = lane + 32 * k;
                float4 a = row4[d];
                float4 s = sv4[d];
                acc = fmaf(a.x, s.x, acc);
                acc = fmaf(a.y, s.y, acc);
                acc = fmaf(a.z, s.z, acc);
                acc = fmaf(a.w, s.w, acc);
            }
            #pragma unroll
            for (int off = 16; off > 0; off >>= 1)
                acc += __shfl_xor_sync(0xFFFFFFFF, acc, off);
            if (lane == 0) g_scores[(size_t)b * L + l0 + l] = acc;
        }
    } else if (blk < SCORE_BLOCKS + ZERO_BLOCKS) {
        // ---- zero block: grid-stride float4 over the whole w_a [B, V_SIZE] ----
        size_t total4 = ((size_t)B * V_SIZE) / 4;          // 1,600,000
        float4* p = reinterpret_cast<float4*>(out);
        size_t idx = (size_t)(blk - SCORE_BLOCKS) * THREADS + tid;
        size_t stride = (size_t)ZERO_BLOCKS * THREADS;
        float4 z = make_float4(0.f, 0.f, 0.f, 0.f);
        for (; idx < total4; idx += stride) p[idx] = z;
    } else {
        // ---- dedup block: compute last-occurrence index row for batch b ----
        int b = blk - SCORE_BLOCKS - ZERO_BLOCKS;
        int xv = (tid < L) ? x[(size_t)b * L + tid] : -1;
        xsh[tid] = xv;
        __syncthreads();

        int last = 1;
        #pragma unroll 8
        for (int l = tid + 1; l < L; l++)
            last &= (xsh[l] != xv);

        if (tid < L)
            g_sidx[(size_t)b * L + tid] = (last && (unsigned)xv < V_SIZE) ? xv : -1;
    }
}

// K2: softmax + masked scatter — no scan, minimal critical path.
__global__ void __launch_bounds__(THREADS)
softmax_scatter_kernel(float* __restrict__ out, int write_tail)
{
    int b = blockIdx.x;
    int tid = threadIdx.x;
    int wid = tid >> 5;
    int lane = tid & 31;

    __shared__ float redm[8];
    __shared__ float reds[8];

    // Two independent loads — latencies overlap.
    float v    = (tid < L) ? g_scores[(size_t)b * L + tid] : -3.402823466e38f;
    int   sidx = (tid < L) ? g_sidx[(size_t)b * L + tid] : -1;

    // Block max (1 barrier).
    float m = v;
    #pragma unroll
    for (int off = 16; off > 0; off >>= 1)
        m = fmaxf(m, __shfl_xor_sync(0xFFFFFFFF, m, off));
    if (lane == 0) redm[wid] = m;
    __syncthreads();
    float mx = redm[0];
    #pragma unroll
    for (int i = 1; i < 8; i++) mx = fmaxf(mx, redm[i]);

    // Block sum of exp (1 barrier).
    float e = (tid < L) ? __expf(v - mx) : 0.f;
    float s = e;
    #pragma unroll
    for (int off = 16; off > 0; off >>= 1)
        s += __shfl_xor_sync(0xFFFFFFFF, s, off);
    if (lane == 0) reds[wid] = s;
    __syncthreads();
    float tot = reds[0];
    #pragma unroll
    for (int i = 1; i < 8; i++) tot += reds[i];

    float w = e * (1.0f / tot);

    if (tid < L) {
        if (write_tail)
            out[(size_t)B * V_SIZE + (size_t)b * L + tid] = w;
        if (sidx >= 0)
            out[(size_t)b * V_SIZE + sidx] = w;
    }
}

extern "C" void kernel_launch(void* const* d_in, const int* in_sizes, int n_in,
                              void* d_out, int out_size)
{
    const float* w_es = (const float*)d_in[0];
    const float* score_v = (const float*)d_in[1];
    const int* x = (const int*)d_in[2];
    float* out = (float*)d_out;

    int write_tail = (out_size >= B * V_SIZE + B * L) ? 1 : 0;

    stream_kernel<<<K1_GRID, THREADS>>>(w_es, score_v, x, out);
    softmax_scatter_kernel<<<B, THREADS>>>(out, write_tail);
}

// round 10
// speedup vs baseline: 1.3662x; 1.1717x over previous
#include <cuda_runtime.h>
#include <cstdint>

#define B 128
#define L 200
#define D 256
#define V_SIZE 50000
#define THREADS 256

#define SPLIT 4                       // score blocks per batch (proven-fast config)
#define ROWS_PER_BLK (L / SPLIT)      // 50
#define SCORE_BLOCKS (B * SPLIT)      // 512
#define ZERO_BLOCKS 1024
#define DEDUP_BLOCKS B                // 128
#define K1_GRID (SCORE_BLOCKS + ZERO_BLOCKS + DEDUP_BLOCKS)   // 1664

__device__ float g_scores[B * L];
__device__ int   g_sidx[B * L];       // last-occurrence ? idx : -1

// K1: [0,512) score blocks; [512,1536) zero blocks; [1536,1664) dedup blocks.
__global__ void __launch_bounds__(THREADS)
stream_kernel(const float* __restrict__ w_es,
              const float* __restrict__ score_v,
              const int* __restrict__ x,
              float* __restrict__ out)
{
    __shared__ __align__(16) float sv[D];        // score path
    __shared__ __align__(16) int   xsh[THREADS]; // dedup path

    int blk = blockIdx.x;
    int tid = threadIdx.x;

    if (blk < SCORE_BLOCKS) {
        // ---- score block: 50 dot products (warp per row, float4) ----
        int b = blk / SPLIT;
        int l0 = (blk % SPLIT) * ROWS_PER_BLK;

        sv[tid] = score_v[tid];       // D == THREADS
        __syncthreads();

        int wid = tid >> 5;
        int lane = tid & 31;
        const float* base = w_es + ((size_t)b * L + l0) * D;
        const float4* sv4 = reinterpret_cast<const float4*>(sv);

        for (int l = wid; l < ROWS_PER_BLK; l += 8) {
            const float4* row4 = reinterpret_cast<const float4*>(base + (size_t)l * D);
            float acc = 0.f;
            #pragma unroll
            for (int k = 0; k < 2; k++) {
                int d = lane + 32 * k;
                float4 a = row4[d];
                float4 s = sv4[d];
                acc = fmaf(a.x, s.x, acc);
                acc = fmaf(a.y, s.y, acc);
                acc = fmaf(a.z, s.z, acc);
                acc = fmaf(a.w, s.w, acc);
            }
            #pragma unroll
            for (int off = 16; off > 0; off >>= 1)
                acc += __shfl_xor_sync(0xFFFFFFFF, acc, off);
            if (lane == 0) g_scores[(size_t)b * L + l0 + l] = acc;
        }
    } else if (blk < SCORE_BLOCKS + ZERO_BLOCKS) {
        // ---- zero block: grid-stride float4 over the whole w_a [B, V_SIZE] ----
        size_t total4 = ((size_t)B * V_SIZE) / 4;          // 1,600,000
        float4* p = reinterpret_cast<float4*>(out);
        size_t idx = (size_t)(blk - SCORE_BLOCKS) * THREADS + tid;
        size_t stride = (size_t)ZERO_BLOCKS * THREADS;
        float4 z = make_float4(0.f, 0.f, 0.f, 0.f);
        for (; idx < total4; idx += stride) p[idx] = z;
    } else {
        // ---- dedup block: last-occurrence index row for batch b ----
        int b = blk - SCORE_BLOCKS - ZERO_BLOCKS;
        int xv = (tid < L) ? x[(size_t)b * L + tid] : -1;
        xsh[tid] = xv;
        __syncthreads();

        int last = 1;
        #pragma unroll 8
        for (int l = tid + 1; l < L; l++)
            last &= (xsh[l] != xv);

        if (tid < L)
            g_sidx[(size_t)b * L + tid] = (last && (unsigned)xv < V_SIZE) ? xv : -1;
    }
}

// K2: softmax + masked scatter — no scan, minimal critical path.
__global__ void __launch_bounds__(THREADS)
softmax_scatter_kernel(float* __restrict__ out, int write_tail)
{
    int b = blockIdx.x;
    int tid = threadIdx.x;
    int wid = tid >> 5;
    int lane = tid & 31;

    __shared__ float redm[8];
    __shared__ float reds[8];

    // Two independent loads — latencies overlap.
    float v    = (tid < L) ? g_scores[(size_t)b * L + tid] : -3.402823466e38f;
    int   sidx = (tid < L) ? g_sidx[(size_t)b * L + tid] : -1;

    // Block max (1 barrier).
    float m = v;
    #pragma unroll
    for (int off = 16; off > 0; off >>= 1)
        m = fmaxf(m, __shfl_xor_sync(0xFFFFFFFF, m, off));
    if (lane == 0) redm[wid] = m;
    __syncthreads();
    float mx = redm[0];
    #pragma unroll
    for (int i = 1; i < 8; i++) mx = fmaxf(mx, redm[i]);

    // Block sum of exp (1 barrier).
    float e = (tid < L) ? __expf(v - mx) : 0.f;
    float s = e;
    #pragma unroll
    for (int off = 16; off > 0; off >>= 1)
        s += __shfl_xor_sync(0xFFFFFFFF, s, off);
    if (lane == 0) reds[wid] = s;
    __syncthreads();
    float tot = reds[0];
    #pragma unroll
    for (int i = 1; i < 8; i++) tot += reds[i];

    float w = e * (1.0f / tot);

    if (tid < L) {
        if (write_tail)
            out[(size_t)B * V_SIZE + (size_t)b * L + tid] = w;
        if (sidx >= 0)
            out[(size_t)b * V_SIZE + sidx] = w;
    }
}

extern "C" void kernel_launch(void* const* d_in, const int* in_sizes, int n_in,
                              void* d_out, int out_size)
{
    const float* w_es = (const float*)d_in[0];
    const float* score_v = (const float*)d_in[1];
    const int* x = (const int*)d_in[2];
    float* out = (float*)d_out;

    int write_tail = (out_size >= B * V_SIZE + B * L) ? 1 : 0;

    stream_kernel<<<K1_GRID, THREADS>>>(w_es, score_v, x, out);
    softmax_scatter_kernel<<<B, THREADS>>>(out, write_tail);
}